// round 1
// baseline (speedup 1.0000x reference)
#include <cuda_runtime.h>
#include <math.h>

// Problem constants
#define BATCH 2
#define SEQ   2048
#define CH    1024
#define HEADS 16
#define HDIM  64
#define MROWS (BATCH*SEQ)   // 4096
#define NQKV  (3*CH)        // 3072
#define HALF  (HDIM/2)      // 32

// Scratch (device globals; no allocation allowed)
__device__ __align__(16) float g_Q[(size_t)BATCH*HEADS*HDIM*SEQ];  // [b][h][d][s]
__device__ __align__(16) float g_K[(size_t)BATCH*HEADS*HDIM*SEQ];  // [b][h][d][s]
__device__ __align__(16) float g_V[(size_t)BATCH*HEADS*SEQ*HDIM];  // [b][h][s][d]
__device__ __align__(16) float g_AO[(size_t)MROWS*CH];             // [b*s][h*d]
__device__ __align__(16) float g_sin[SEQ*HALF];
__device__ __align__(16) float g_cos[SEQ*HALF];

// ---------------------------------------------------------------------------
// RoPE table: sin/cos of ang = s / 10000^(p/32), fp32 to match reference math
// ---------------------------------------------------------------------------
__global__ void rope_table_kernel() {
    int idx = blockIdx.x * blockDim.x + threadIdx.x;   // s*32 + p
    if (idx < SEQ * HALF) {
        int s = idx >> 5;
        int p = idx & 31;
        float dim_t = powf(10000.0f, (float)p / (float)HALF);
        float ang = (float)s / dim_t;
        g_sin[idx] = sinf(ang);
        g_cos[idx] = cosf(ang);
    }
}

// ---------------------------------------------------------------------------
// Tiled SGEMM, 128x128 block, 8x8 per thread, 256 threads, K-chunk 8.
// MODE 1: C = x @ w_qkv, epilogue adds q/v bias, applies RoPE to Q/K,
//         folds 1/sqrt(D) into Q, writes Q,K transposed [b][h][d][s], V [b][h][s][d].
// MODE 0: C = g_AO @ w_out -> Cout (d_out).
// ---------------------------------------------------------------------------
template <int MODE>
__global__ __launch_bounds__(256)
void gemm_kernel(const float* __restrict__ A, const float* __restrict__ Bm,
                 float* __restrict__ Cout,
                 const float* __restrict__ qb, const float* __restrict__ vb,
                 int K, int N)
{
    __shared__ float As[8][128];   // [kk][m]
    __shared__ float Bs[8][128];   // [kk][n]

    const int tid = threadIdx.x;
    const int tx = tid & 15;
    const int ty = tid >> 4;
    const int mBlock = blockIdx.y * 128;
    const int nBlock = blockIdx.x * 128;

    const float* Ap = (MODE == 0) ? g_AO : A;

    const float* Aload = Ap + (size_t)(mBlock + (tid >> 1)) * K + ((tid & 1) << 2);
    const float* Bload = Bm + (size_t)(tid >> 5) * N + nBlock + ((tid & 31) << 2);

    float acc[8][8];
    #pragma unroll
    for (int i = 0; i < 8; i++)
        #pragma unroll
        for (int j = 0; j < 8; j++) acc[i][j] = 0.0f;

    const int am = tid >> 1;
    const int ak = (tid & 1) << 2;
    const int bn = (tid & 31) << 2;
    const int bk = tid >> 5;

    float4 av = *(const float4*)(Aload);
    float4 bv = *(const float4*)(Bload);

    for (int kt = 0; kt < K; kt += 8) {
        __syncthreads();
        As[ak + 0][am] = av.x;
        As[ak + 1][am] = av.y;
        As[ak + 2][am] = av.z;
        As[ak + 3][am] = av.w;
        *(float4*)&Bs[bk][bn] = bv;
        __syncthreads();
        if (kt + 8 < K) {
            av = *(const float4*)(Aload + kt + 8);
            bv = *(const float4*)(Bload + (size_t)(kt + 8) * N);
        }
        #pragma unroll
        for (int kk = 0; kk < 8; kk++) {
            float a[8], b[8];
            *(float4*)&a[0] = *(float4*)&As[kk][ty * 8];
            *(float4*)&a[4] = *(float4*)&As[kk][ty * 8 + 4];
            *(float4*)&b[0] = *(float4*)&Bs[kk][tx * 8];
            *(float4*)&b[4] = *(float4*)&Bs[kk][tx * 8 + 4];
            #pragma unroll
            for (int i = 0; i < 8; i++)
                #pragma unroll
                for (int j = 0; j < 8; j++)
                    acc[i][j] = fmaf(a[i], b[j], acc[i][j]);
        }
    }

    const int m0 = mBlock + ty * 8;
    const int n0 = nBlock + tx * 8;

    if (MODE == 0) {
        #pragma unroll
        for (int i = 0; i < 8; i++) {
            float4 lo = make_float4(acc[i][0], acc[i][1], acc[i][2], acc[i][3]);
            float4 hi = make_float4(acc[i][4], acc[i][5], acc[i][6], acc[i][7]);
            float* dst = Cout + (size_t)(m0 + i) * N + n0;
            *(float4*)dst = lo;
            *(float4*)(dst + 4) = hi;
        }
    } else {
        const int bIdx  = m0 >> 11;          // batch
        const int s0    = m0 & (SEQ - 1);    // seq base (8 consecutive)
        const int sec   = n0 >> 10;          // 0=q 1=k 2=v
        const int c0    = n0 & (CH - 1);
        const int h     = c0 >> 6;
        const int dbase = c0 & 63;           // multiple of 8
        const size_t bh = (size_t)(bIdx * HEADS + h);

        if (sec == 2) {
            float vb8[8];
            #pragma unroll
            for (int j = 0; j < 8; j++) vb8[j] = vb[c0 + j];
            #pragma unroll
            for (int i = 0; i < 8; i++) {
                float4 lo = make_float4(acc[i][0] + vb8[0], acc[i][1] + vb8[1],
                                        acc[i][2] + vb8[2], acc[i][3] + vb8[3]);
                float4 hi = make_float4(acc[i][4] + vb8[4], acc[i][5] + vb8[5],
                                        acc[i][6] + vb8[6], acc[i][7] + vb8[7]);
                float* dst = g_V + (bh * SEQ + (size_t)(s0 + i)) * HDIM + dbase;
                *(float4*)dst = lo;
                *(float4*)(dst + 4) = hi;
            }
        } else {
            if (sec == 0) {
                float qb8[8];
                #pragma unroll
                for (int j = 0; j < 8; j++) qb8[j] = qb[c0 + j];
                #pragma unroll
                for (int i = 0; i < 8; i++)
                    #pragma unroll
                    for (int j = 0; j < 8; j++) acc[i][j] += qb8[j];
            }
            // RoPE in place (pairs of adjacent d)
            const int pbase = dbase >> 1;
            #pragma unroll
            for (int i = 0; i < 8; i++) {
                const int s = s0 + i;
                const float* srow = &g_sin[s * HALF + pbase];
                const float* crow = &g_cos[s * HALF + pbase];
                #pragma unroll
                for (int jp = 0; jp < 4; jp++) {
                    float v0 = acc[i][2 * jp];
                    float v1 = acc[i][2 * jp + 1];
                    float sn = srow[jp];
                    float cs = crow[jp];
                    acc[i][2 * jp]     = v0 * cs - v1 * sn;
                    acc[i][2 * jp + 1] = v1 * cs + v0 * sn;
                }
                if (sec == 0) {
                    #pragma unroll
                    for (int j = 0; j < 8; j++) acc[i][j] *= 0.125f;  // 1/sqrt(64)
                }
            }
            float* base = (sec == 0 ? g_Q : g_K) + (bh * HDIM) * (size_t)SEQ + s0;
            #pragma unroll
            for (int j = 0; j < 8; j++) {
                float4 lo = make_float4(acc[0][j], acc[1][j], acc[2][j], acc[3][j]);
                float4 hi = make_float4(acc[4][j], acc[5][j], acc[6][j], acc[7][j]);
                float* dst = base + (size_t)(dbase + j) * SEQ;
                *(float4*)dst = lo;
                *(float4*)(dst + 4) = hi;
            }
        }
    }
}

// ---------------------------------------------------------------------------
// Flash attention, fp32, 64x64 tiles, online softmax, causal.
// Q/K read from transposed [b][h][d][s]; V from [b][h][s][d].
// Thread layout 16x16, each thread owns a 4x4 microtile.
// P tile reuses the K smem buffer with a 4-float-chunk XOR swizzle.
// ---------------------------------------------------------------------------
__global__ __launch_bounds__(256)
void flash_kernel()
{
    __shared__ float Qs[64 * 64];   // [d][r]
    __shared__ float KPs[64 * 64];  // K: [d][c];  P: swizzled [c][r]
    __shared__ float Vs[64 * 64];   // [k][d]

    const int tid = threadIdx.x;
    const int tx = tid & 15;
    const int ty = tid >> 4;
    const int bh = blockIdx.y;
    const int qt = (gridDim.x - 1) - blockIdx.x;  // largest tiles first
    const int q0 = qt * 64;

    const float* Qb = g_Q + (size_t)bh * HDIM * SEQ;
    const float* Kb = g_K + (size_t)bh * HDIM * SEQ;
    const float* Vb = g_V + (size_t)bh * SEQ * HDIM;

    #pragma unroll
    for (int slot = tid; slot < 1024; slot += 256) {
        int d = slot >> 4, r4 = (slot & 15) << 2;
        *(float4*)&Qs[d * 64 + r4] = *(const float4*)&Qb[(size_t)d * SEQ + q0 + r4];
    }

    float m_i[4], l_i[4], o[4][4];
    #pragma unroll
    for (int i = 0; i < 4; i++) {
        m_i[i] = -1e30f;
        l_i[i] = 0.0f;
        #pragma unroll
        for (int j = 0; j < 4; j++) o[i][j] = 0.0f;
    }
    __syncthreads();

    for (int kt = 0; kt <= qt; kt++) {
        const int k0 = kt * 64;
        #pragma unroll
        for (int slot = tid; slot < 1024; slot += 256) {
            int d = slot >> 4, c4 = (slot & 15) << 2;
            *(float4*)&KPs[d * 64 + c4] = *(const float4*)&Kb[(size_t)d * SEQ + k0 + c4];
            *(float4*)&Vs[d * 64 + c4]  = *(const float4*)&Vb[(size_t)(k0 + d) * HDIM + c4];
        }
        __syncthreads();

        // S = Q K^T (scale already folded into Q)
        float sacc[4][4];
        #pragma unroll
        for (int i = 0; i < 4; i++)
            #pragma unroll
            for (int j = 0; j < 4; j++) sacc[i][j] = 0.0f;

        #pragma unroll 8
        for (int d = 0; d < 64; d++) {
            float q4[4], k4[4];
            *(float4*)q4 = *(const float4*)&Qs[d * 64 + ty * 4];
            *(float4*)k4 = *(const float4*)&KPs[d * 64 + tx * 4];
            #pragma unroll
            for (int i = 0; i < 4; i++)
                #pragma unroll
                for (int j = 0; j < 4; j++)
                    sacc[i][j] = fmaf(q4[i], k4[j], sacc[i][j]);
        }

        if (kt == qt) {  // causal mask on diagonal tile
            #pragma unroll
            for (int i = 0; i < 4; i++)
                #pragma unroll
                for (int j = 0; j < 4; j++)
                    if (tx * 4 + j > ty * 4 + i) sacc[i][j] = -1e30f;
        }

        // online softmax update (row reduce over 16 lanes sharing ty)
        #pragma unroll
        for (int i = 0; i < 4; i++) {
            float mx = fmaxf(fmaxf(sacc[i][0], sacc[i][1]), fmaxf(sacc[i][2], sacc[i][3]));
            #pragma unroll
            for (int ofs = 1; ofs < 16; ofs <<= 1)
                mx = fmaxf(mx, __shfl_xor_sync(0xffffffffu, mx, ofs));
            float mn = fmaxf(m_i[i], mx);
            float al = __expf(m_i[i] - mn);
            float sum = 0.0f;
            #pragma unroll
            for (int j = 0; j < 4; j++) {
                float p = __expf(sacc[i][j] - mn);
                sacc[i][j] = p;
                sum += p;
            }
            #pragma unroll
            for (int ofs = 1; ofs < 16; ofs <<= 1)
                sum += __shfl_xor_sync(0xffffffffu, sum, ofs);
            l_i[i] = l_i[i] * al + sum;
            m_i[i] = mn;
            #pragma unroll
            for (int j = 0; j < 4; j++) o[i][j] *= al;
        }

        __syncthreads();  // done reading K from KPs
        // store P swizzled: logical P[c][r], chunk index (r>>2) ^ (c&15)
        #pragma unroll
        for (int j = 0; j < 4; j++) {
            int c = tx * 4 + j;
            int base = c * 64 + ((ty ^ (c & 15)) << 2);
            #pragma unroll
            for (int i = 0; i < 4; i++) KPs[base + i] = sacc[i][j];
        }
        __syncthreads();

        // O += P V
        #pragma unroll 8
        for (int k = 0; k < 64; k++) {
            float p4[4], v4[4];
            *(float4*)p4 = *(const float4*)&KPs[k * 64 + ((ty ^ (k & 15)) << 2)];
            *(float4*)v4 = *(const float4*)&Vs[k * 64 + tx * 4];
            #pragma unroll
            for (int i = 0; i < 4; i++)
                #pragma unroll
                for (int j = 0; j < 4; j++)
                    o[i][j] = fmaf(p4[i], v4[j], o[i][j]);
        }
        __syncthreads();
    }

    const int b = bh >> 4;
    const int h = bh & 15;
    #pragma unroll
    for (int i = 0; i < 4; i++) {
        float inv = 1.0f / l_i[i];
        int s = q0 + ty * 4 + i;
        float4 r = make_float4(o[i][0] * inv, o[i][1] * inv,
                               o[i][2] * inv, o[i][3] * inv);
        *(float4*)&g_AO[(size_t)(b * SEQ + s) * CH + h * 64 + tx * 4] = r;
    }
}

// ---------------------------------------------------------------------------
extern "C" void kernel_launch(void* const* d_in, const int* in_sizes, int n_in,
                              void* d_out, int out_size)
{
    const float* x      = (const float*)d_in[0];
    const float* w_qkv  = (const float*)d_in[1];
    const float* q_bias = (const float*)d_in[2];
    const float* v_bias = (const float*)d_in[3];
    const float* w_out  = (const float*)d_in[4];
    float* out = (float*)d_out;

    rope_table_kernel<<<SEQ * HALF / 256, 256>>>();

    // QKV projection + bias + RoPE + scale, writes g_Q/g_K (transposed) and g_V
    gemm_kernel<1><<<dim3(NQKV / 128, MROWS / 128), 256>>>(
        x, w_qkv, nullptr, q_bias, v_bias, CH, NQKV);

    // causal flash attention -> g_AO
    flash_kernel<<<dim3(SEQ / 64, BATCH * HEADS), 256>>>();

    // output projection -> d_out
    gemm_kernel<0><<<dim3(CH / 128, MROWS / 128), 256>>>(
        nullptr, w_out, out, nullptr, nullptr, CH, CH);
}